// round 2
// baseline (speedup 1.0000x reference)
#include <cuda_runtime.h>
#include <cfloat>

// Global accumulator (no device allocation allowed).
__device__ double g_hpwl_accum;

__global__ void hpwl_init_kernel() {
    g_hpwl_accum = 0.0;
}

__global__ void hpwl_main_kernel(const float* __restrict__ pos,
                                 const int* __restrict__ flat_netpin,
                                 const int* __restrict__ netpin_start,
                                 const int* __restrict__ ignore_ptr,
                                 int num_nets, int num_pins)
{
    const int i = blockIdx.x * blockDim.x + threadIdx.x;
    const int ignore_deg = *ignore_ptr;

    float local = 0.0f;
    if (i < num_nets) {
        const int s = netpin_start[i];
        const int e = netpin_start[i + 1];
        const int deg = e - s;
        if (deg > 0 && deg <= ignore_deg) {
            float xmin = FLT_MAX, xmax = -FLT_MAX;
            float ymin = FLT_MAX, ymax = -FLT_MAX;
            for (int j = s; j < e; ++j) {
                const int p = __ldg(flat_netpin + j);
                const float x = __ldg(pos + p);
                const float y = __ldg(pos + num_pins + p);
                xmin = fminf(xmin, x);
                xmax = fmaxf(xmax, x);
                ymin = fminf(ymin, y);
                ymax = fmaxf(ymax, y);
            }
            local = (xmax - xmin) + (ymax - ymin);
        }
    }

    // Warp reduction
    #pragma unroll
    for (int off = 16; off > 0; off >>= 1)
        local += __shfl_down_sync(0xFFFFFFFFu, local, off);

    if ((threadIdx.x & 31) == 0 && local != 0.0f)
        atomicAdd(&g_hpwl_accum, (double)local);
}

__global__ void hpwl_write_kernel(float* __restrict__ out) {
    out[0] = (float)g_hpwl_accum;
}

extern "C" void kernel_launch(void* const* d_in, const int* in_sizes, int n_in,
                              void* d_out, int out_size)
{
    const float* pos       = (const float*)d_in[0];
    const int* flat        = (const int*)d_in[1];
    const int* start       = (const int*)d_in[2];
    const int* ignore_ptr  = (const int*)d_in[3];

    const int num_pins = in_sizes[1];
    const int num_nets = in_sizes[2] - 1;

    hpwl_init_kernel<<<1, 1>>>();

    const int threads = 256;
    const int blocks = (num_nets + threads - 1) / threads;
    hpwl_main_kernel<<<blocks, threads>>>(pos, flat, start, ignore_ptr,
                                          num_nets, num_pins);

    hpwl_write_kernel<<<1, 1>>>((float*)d_out);
}

// round 3
// speedup vs baseline: 1.6179x; 1.6179x over previous
#include <cuda_runtime.h>
#include <cfloat>

// Self-restoring global state (zero at module load; last block resets it each
// call, so every graph replay sees identical initial state).
__device__ double g_hpwl_accum = 0.0;
__device__ unsigned int g_block_count = 0u;

__global__ void __launch_bounds__(256) hpwl_kernel(
    const float* __restrict__ pos,
    const int* __restrict__ flat_netpin,
    const int* __restrict__ netpin_start,
    const int* __restrict__ ignore_ptr,
    int num_nets, int num_pins,
    float* __restrict__ out)
{
    __shared__ float s_warp[8];
    const int i = blockIdx.x * blockDim.x + threadIdx.x;
    const int ignore_deg = *ignore_ptr;

    float local = 0.0f;
    if (i < num_nets) {
        const int s = netpin_start[i];
        const int e = netpin_start[i + 1];
        const int deg = e - s;
        if (deg > 0 && deg <= ignore_deg) {
            float xmin = FLT_MAX, xmax = -FLT_MAX;
            float ymin = FLT_MAX, ymax = -FLT_MAX;
            // Full unroll (deg <= 8 by construction): front-batches the index
            // loads and exposes all gathers as independent in-flight LDGs.
            #pragma unroll
            for (int k = 0; k < 8; ++k) {
                if (k < deg) {
                    const int p = __ldg(flat_netpin + s + k);
                    const float x = __ldg(pos + p);
                    const float y = __ldg(pos + num_pins + p);
                    xmin = fminf(xmin, x);
                    xmax = fmaxf(xmax, x);
                    ymin = fminf(ymin, y);
                    ymax = fmaxf(ymax, y);
                }
            }
            local = (xmax - xmin) + (ymax - ymin);
        }
    }

    // Warp reduce
    #pragma unroll
    for (int off = 16; off > 0; off >>= 1)
        local += __shfl_down_sync(0xFFFFFFFFu, local, off);

    const int lane = threadIdx.x & 31;
    const int wid  = threadIdx.x >> 5;
    if (lane == 0) s_warp[wid] = local;
    __syncthreads();

    if (wid == 0) {
        float v = (lane < 8) ? s_warp[lane] : 0.0f;
        #pragma unroll
        for (int off = 4; off > 0; off >>= 1)
            v += __shfl_down_sync(0xFFFFFFFFu, v, off);

        if (lane == 0) {
            atomicAdd(&g_hpwl_accum, (double)v);
            __threadfence();
            const unsigned int done = atomicAdd(&g_block_count, 1u);
            if (done == gridDim.x - 1) {
                // Last block: publish result and restore state for the next
                // (graph-replayed) call.
                out[0] = (float)g_hpwl_accum;
                g_hpwl_accum = 0.0;
                g_block_count = 0u;
            }
        }
    }
}

extern "C" void kernel_launch(void* const* d_in, const int* in_sizes, int n_in,
                              void* d_out, int out_size)
{
    const float* pos       = (const float*)d_in[0];
    const int* flat        = (const int*)d_in[1];
    const int* start       = (const int*)d_in[2];
    const int* ignore_ptr  = (const int*)d_in[3];

    const int num_pins = in_sizes[1];
    const int num_nets = in_sizes[2] - 1;

    const int threads = 256;
    const int blocks = (num_nets + threads - 1) / threads;
    hpwl_kernel<<<blocks, threads>>>(pos, flat, start, ignore_ptr,
                                     num_nets, num_pins, (float*)d_out);
}